// round 1
// baseline (speedup 1.0000x reference)
#include <cuda_runtime.h>
#include <math.h>

// Problem constants
constexpr int SEQ   = 1024;
constexpr int DM    = 1024;
constexpr int NHEAD = 16;
constexpr int HDIM  = 64;
constexpr int NB    = 4;
constexpr int MR    = NB * SEQ;   // 4096 rows for the big GEMMs

// ---------------- scratch (device globals; no allocation allowed) ----------
__device__ float g_q [(size_t)MR * DM];
__device__ float g_k [(size_t)MR * DM];
__device__ float g_v [(size_t)MR * DM];
__device__ float g_s [(size_t)NB * NHEAD * SEQ * SEQ];   // raw scores (b,h,q,j)
__device__ float g_att[(size_t)NHEAD * SEQ * SEQ];       // batch-summed probs (h,q,j)
__device__ float g_av[(size_t)MR * DM];                  // attention output pre-proj

// ===========================================================================
// GEMM: C[i,j] = sum_k A[i,k] * W[j,k] + bias[j]
// A: MxK row-major, W: NxK row-major (i.e. C = A @ W^T + b)
// 128x128 tile, Ktile=16, 256 threads, 8x8 per thread.
// M % 128 == 0, N % 128 == 0, K % 16 == 0 assumed.
// ===========================================================================
__global__ __launch_bounds__(256) void gemm_bias_kernel(
    const float* __restrict__ A, const float* __restrict__ W,
    const float* __restrict__ bias, float* __restrict__ C,
    int M, int N, int K)
{
    __shared__ float As[16][128];
    __shared__ float Ws[16][128];

    const int tid = threadIdx.x;
    const int bm  = blockIdx.y * 128;
    const int bn  = blockIdx.x * 128;
    const int ty  = tid >> 4;     // 0..15
    const int tx  = tid & 15;     // 0..15

    float acc[8][8];
#pragma unroll
    for (int i = 0; i < 8; i++)
#pragma unroll
        for (int j = 0; j < 8; j++) acc[i][j] = 0.f;

    for (int k0 = 0; k0 < K; k0 += 16) {
#pragma unroll
        for (int i = 0; i < 2; i++) {
            int idx = tid + i * 256;           // 0..511
            int row = idx >> 2;                // 0..127
            int kc  = (idx & 3) << 2;          // 0,4,8,12
            float4 va = *(const float4*)(A + (size_t)(bm + row) * K + k0 + kc);
            As[kc + 0][row] = va.x; As[kc + 1][row] = va.y;
            As[kc + 2][row] = va.z; As[kc + 3][row] = va.w;
            float4 vw = *(const float4*)(W + (size_t)(bn + row) * K + k0 + kc);
            Ws[kc + 0][row] = vw.x; Ws[kc + 1][row] = vw.y;
            Ws[kc + 2][row] = vw.z; Ws[kc + 3][row] = vw.w;
        }
        __syncthreads();

#pragma unroll
        for (int kk = 0; kk < 16; kk++) {
            float a[8], b[8];
            *(float4*)(a)     = *(const float4*)&As[kk][ty * 8];
            *(float4*)(a + 4) = *(const float4*)&As[kk][ty * 8 + 4];
            *(float4*)(b)     = *(const float4*)&Ws[kk][tx * 8];
            *(float4*)(b + 4) = *(const float4*)&Ws[kk][tx * 8 + 4];
#pragma unroll
            for (int i = 0; i < 8; i++)
#pragma unroll
                for (int j = 0; j < 8; j++) acc[i][j] += a[i] * b[j];
        }
        __syncthreads();
    }

    float bvals[8];
#pragma unroll
    for (int j = 0; j < 8; j++) bvals[j] = bias[bn + tx * 8 + j];

#pragma unroll
    for (int i = 0; i < 8; i++) {
        int r = bm + ty * 8 + i;
#pragma unroll
        for (int j = 0; j < 8; j += 4) {
            float4 o;
            o.x = acc[i][j + 0] + bvals[j + 0];
            o.y = acc[i][j + 1] + bvals[j + 1];
            o.z = acc[i][j + 2] + bvals[j + 2];
            o.w = acc[i][j + 3] + bvals[j + 3];
            *(float4*)(C + (size_t)r * N + bn + tx * 8 + j) = o;
        }
    }
}

// ===========================================================================
// Scores: s[b,h,qi,j] = (q_row . k_row) / 8
// block tile: 128 q-rows x 64 j-cols, K = 64 (full head dim), 256 threads.
// grid: (16 jtiles, 8 qtiles, 64 bh)
// ===========================================================================
__global__ __launch_bounds__(256) void scores_kernel(
    const float* __restrict__ q, const float* __restrict__ k,
    float* __restrict__ s)
{
    __shared__ float Qs[64][128];   // [kdim][qrow]
    __shared__ float Ks[64][64];    // [kdim][jcol]

    const int bh = blockIdx.z;
    const int b  = bh >> 4;
    const int h  = bh & 15;
    const int q0 = blockIdx.y * 128;
    const int j0 = blockIdx.x * 64;
    const int tid = threadIdx.x;

    const float* qb = q + ((size_t)(b * SEQ + q0)) * DM + h * HDIM;
    const float* kb = k + ((size_t)(b * SEQ + j0)) * DM + h * HDIM;

    // Q tile: 128 rows x 64 = 2048 float4; lane-major-in-row mapping ->
    // conflict-free transposed smem stores (global gather is L1/L2-absorbed).
#pragma unroll
    for (int i = 0; i < 8; i++) {
        int idx = tid + i * 256;
        int row = idx & 127;
        int kg  = idx >> 7;            // 0..15
        float4 v4 = *(const float4*)(qb + (size_t)row * DM + kg * 4);
        Qs[kg * 4 + 0][row] = v4.x; Qs[kg * 4 + 1][row] = v4.y;
        Qs[kg * 4 + 2][row] = v4.z; Qs[kg * 4 + 3][row] = v4.w;
    }
#pragma unroll
    for (int i = 0; i < 4; i++) {
        int idx = tid + i * 256;
        int row = idx & 63;
        int kg  = idx >> 6;            // 0..15
        float4 v4 = *(const float4*)(kb + (size_t)row * DM + kg * 4);
        Ks[kg * 4 + 0][row] = v4.x; Ks[kg * 4 + 1][row] = v4.y;
        Ks[kg * 4 + 2][row] = v4.z; Ks[kg * 4 + 3][row] = v4.w;
    }
    __syncthreads();

    const int ty = tid >> 4;   // q-row group (x8)
    const int tx = tid & 15;   // j-col group (x4)
    float acc[8][4];
#pragma unroll
    for (int i = 0; i < 8; i++)
#pragma unroll
        for (int j = 0; j < 4; j++) acc[i][j] = 0.f;

#pragma unroll 8
    for (int kk = 0; kk < 64; kk++) {
        float a[8], bb[4];
        *(float4*)(a)     = *(const float4*)&Qs[kk][ty * 8];
        *(float4*)(a + 4) = *(const float4*)&Qs[kk][ty * 8 + 4];
        *(float4*)(bb)    = *(const float4*)&Ks[kk][tx * 4];
#pragma unroll
        for (int i = 0; i < 8; i++)
#pragma unroll
            for (int j = 0; j < 4; j++) acc[i][j] += a[i] * bb[j];
    }

    float* outp = s + ((size_t)bh * SEQ + q0) * SEQ + j0;
#pragma unroll
    for (int i = 0; i < 8; i++) {
        int row = ty * 8 + i;
        float4 o;
        o.x = acc[i][0] * 0.125f;
        o.y = acc[i][1] * 0.125f;
        o.z = acc[i][2] * 0.125f;
        o.w = acc[i][3] * 0.125f;
        *(float4*)(outp + (size_t)row * SEQ + tx * 4) = o;
    }
}

// ===========================================================================
// Softmax over j (+mask), NaN->0, sum over batch:
// att[h,qi,j] = sum_b exp(s[b,h,qi,j]+mask[qi,j]-m_b)/Z_b
// one block per (h,qi); 256 threads, 4 j per thread held in registers.
// ===========================================================================
__global__ __launch_bounds__(256) void softmax_sum_kernel(
    const float* __restrict__ s, const float* __restrict__ mask,
    float* __restrict__ att)
{
    __shared__ float red[8];

    const int h   = blockIdx.x >> 10;
    const int qi  = blockIdx.x & 1023;
    const int tid = threadIdx.x;
    const int lane = tid & 31;
    const int warp = tid >> 5;

    float mv[4];
#pragma unroll
    for (int u = 0; u < 4; u++) mv[u] = mask[(size_t)qi * SEQ + tid + u * 256];

    float facc[4] = {0.f, 0.f, 0.f, 0.f};

    for (int b = 0; b < NB; b++) {
        const float* srow = s + (((size_t)(b * NHEAD + h)) * SEQ + qi) * SEQ;
        float rv[4];
        float m = -INFINITY;
#pragma unroll
        for (int u = 0; u < 4; u++) {
            rv[u] = srow[tid + u * 256] + mv[u];
            m = fmaxf(m, rv[u]);
        }
        // block max
#pragma unroll
        for (int o = 16; o > 0; o >>= 1) m = fmaxf(m, __shfl_xor_sync(0xffffffffu, m, o));
        __syncthreads();                 // protect red from previous iteration
        if (lane == 0) red[warp] = m;
        __syncthreads();
        m = red[0];
#pragma unroll
        for (int w = 1; w < 8; w++) m = fmaxf(m, red[w]);

        float ssum = 0.f;
#pragma unroll
        for (int u = 0; u < 4; u++) {
            rv[u] = __expf(rv[u] - m);
            ssum += rv[u];
        }
#pragma unroll
        for (int o = 16; o > 0; o >>= 1) ssum += __shfl_xor_sync(0xffffffffu, ssum, o);
        __syncthreads();                 // protect red (max phase) before reuse
        if (lane == 0) red[warp] = ssum;
        __syncthreads();
        ssum = 0.f;
#pragma unroll
        for (int w = 0; w < 8; w++) ssum += red[w];

        if (ssum > 0.f && isfinite(ssum)) {
            float inv = 1.f / ssum;
#pragma unroll
            for (int u = 0; u < 4; u++) facc[u] += rv[u] * inv;
        }
        // else: whole row NaN in reference -> contributes 0 (nan_to_num)
    }

    float* arow = att + ((size_t)h * SEQ + qi) * SEQ;
#pragma unroll
    for (int u = 0; u < 4; u++) arow[tid + u * 256] = facc[u];
}

// ===========================================================================
// AV: out[b, m, h*64+d] = sum_j att[h,m,j] * v[b, j, h*64+d]
// block tile: 128 m-rows x 64 d-cols, Ktile=16, 256 threads.
// grid: (8 mtiles, 64 bh)
// ===========================================================================
__global__ __launch_bounds__(256) void av_kernel(
    const float* __restrict__ att, const float* __restrict__ v,
    float* __restrict__ out)
{
    __shared__ float As[16][128];   // [j][m]
    __shared__ float Vs[16][64];    // [j][d]

    const int bh = blockIdx.y;
    const int b  = bh >> 4;
    const int h  = bh & 15;
    const int m0 = blockIdx.x * 128;
    const int tid = threadIdx.x;
    const int ty = tid >> 4;
    const int tx = tid & 15;

    const float* ab = att + ((size_t)h * SEQ + m0) * SEQ;
    const float* vb = v + (size_t)b * SEQ * DM + h * HDIM;

    float acc[8][4];
#pragma unroll
    for (int i = 0; i < 8; i++)
#pragma unroll
        for (int j = 0; j < 4; j++) acc[i][j] = 0.f;

    for (int k0 = 0; k0 < SEQ; k0 += 16) {
        // att tile 128x16 = 512 float4 (conflict-free transposed stores)
#pragma unroll
        for (int i = 0; i < 2; i++) {
            int idx = tid + i * 256;
            int row = idx & 127;
            int kg  = idx >> 7;       // 0..3
            float4 a4 = *(const float4*)(ab + (size_t)row * SEQ + k0 + kg * 4);
            As[kg * 4 + 0][row] = a4.x; As[kg * 4 + 1][row] = a4.y;
            As[kg * 4 + 2][row] = a4.z; As[kg * 4 + 3][row] = a4.w;
        }
        // v tile 16x64 = 256 float4, one per thread, natural layout
        {
            int vr = tid >> 4;        // 0..15 (j)
            int vc = (tid & 15) << 2; // 0..60 (d)
            float4 v4 = *(const float4*)(vb + (size_t)(k0 + vr) * DM + vc);
            Vs[vr][vc + 0] = v4.x; Vs[vr][vc + 1] = v4.y;
            Vs[vr][vc + 2] = v4.z; Vs[vr][vc + 3] = v4.w;
        }
        __syncthreads();

#pragma unroll
        for (int kk = 0; kk < 16; kk++) {
            float a[8], bb[4];
            *(float4*)(a)     = *(const float4*)&As[kk][ty * 8];
            *(float4*)(a + 4) = *(const float4*)&As[kk][ty * 8 + 4];
            *(float4*)(bb)    = *(const float4*)&Vs[kk][tx * 4];
#pragma unroll
            for (int i = 0; i < 8; i++)
#pragma unroll
                for (int j = 0; j < 4; j++) acc[i][j] += a[i] * bb[j];
        }
        __syncthreads();
    }

    float* ob = out + ((size_t)(b * SEQ + m0)) * DM + h * HDIM;
#pragma unroll
    for (int i = 0; i < 8; i++) {
        float4 o;
        o.x = acc[i][0]; o.y = acc[i][1]; o.z = acc[i][2]; o.w = acc[i][3];
        *(float4*)(ob + (size_t)(ty * 8 + i) * DM + tx * 4) = o;
    }
}

// ===========================================================================
extern "C" void kernel_launch(void* const* d_in, const int* in_sizes, int n_in,
                              void* d_out, int out_size)
{
    const float* x    = (const float*)d_in[0];
    const float* y    = (const float*)d_in[1];
    const float* mask = (const float*)d_in[2];
    const float* Wq   = (const float*)d_in[3];
    const float* bq   = (const float*)d_in[4];
    const float* Wk   = (const float*)d_in[5];
    const float* bk   = (const float*)d_in[6];
    const float* Wv   = (const float*)d_in[7];
    const float* bv   = (const float*)d_in[8];
    const float* Wo   = (const float*)d_in[9];
    const float* bo   = (const float*)d_in[10];
    float* out = (float*)d_out;

    float *q, *k, *v, *sc, *att, *av;
    cudaGetSymbolAddress((void**)&q,   g_q);
    cudaGetSymbolAddress((void**)&k,   g_k);
    cudaGetSymbolAddress((void**)&v,   g_v);
    cudaGetSymbolAddress((void**)&sc,  g_s);
    cudaGetSymbolAddress((void**)&att, g_att);
    cudaGetSymbolAddress((void**)&av,  g_av);

    dim3 ggrid(DM / 128, MR / 128);   // (8, 32)

    gemm_bias_kernel<<<ggrid, 256>>>(y, Wq, bq, q, MR, DM, DM);
    gemm_bias_kernel<<<ggrid, 256>>>(x, Wk, bk, k, MR, DM, DM);
    gemm_bias_kernel<<<ggrid, 256>>>(x, Wv, bv, v, MR, DM, DM);

    scores_kernel<<<dim3(SEQ / 64, SEQ / 128, NB * NHEAD), 256>>>(q, k, sc);

    softmax_sum_kernel<<<NHEAD * SEQ, 256>>>(sc, mask, att);

    av_kernel<<<dim3(SEQ / 128, NB * NHEAD), 256>>>(att, v, av);

    gemm_bias_kernel<<<ggrid, 256>>>(av, Wo, bo, out, MR, DM, DM);
}

// round 4
// speedup vs baseline: 1.4482x; 1.4482x over previous
#include <cuda_runtime.h>
#include <cuda_bf16.h>
#include <math.h>
#include <stdint.h>

// Problem constants
constexpr int SEQ   = 1024;
constexpr int DM    = 1024;
constexpr int NHEAD = 16;
constexpr int HDIM  = 64;
constexpr int NB    = 4;
constexpr int MR    = NB * SEQ;   // 4096 rows for the big GEMMs

// ---------------- scratch (device globals; no allocation allowed) ----------
__device__ float g_q [(size_t)MR * DM];
__device__ float g_k [(size_t)MR * DM];
__device__ float g_v [(size_t)MR * DM];
__device__ float g_s [(size_t)NB * NHEAD * SEQ * SEQ];   // raw scores (b,h,q,j)
__device__ float g_att[(size_t)NHEAD * SEQ * SEQ];       // batch-summed probs (h,q,j)
__device__ float g_av[(size_t)MR * DM];                  // attention output pre-proj

// bf16 hi/lo splits for tensor-core GEMMs
__device__ __nv_bfloat16 g_yh[(size_t)MR * DM];
__device__ __nv_bfloat16 g_yl[(size_t)MR * DM];
__device__ __nv_bfloat16 g_xh[(size_t)MR * DM];
__device__ __nv_bfloat16 g_xl[(size_t)MR * DM];
__device__ __nv_bfloat16 g_avh[(size_t)MR * DM];
__device__ __nv_bfloat16 g_avl[(size_t)MR * DM];
__device__ __nv_bfloat16 g_wqh[(size_t)DM * DM];
__device__ __nv_bfloat16 g_wql[(size_t)DM * DM];
__device__ __nv_bfloat16 g_wkh[(size_t)DM * DM];
__device__ __nv_bfloat16 g_wkl[(size_t)DM * DM];
__device__ __nv_bfloat16 g_wvh[(size_t)DM * DM];
__device__ __nv_bfloat16 g_wvl[(size_t)DM * DM];
__device__ __nv_bfloat16 g_woh[(size_t)DM * DM];
__device__ __nv_bfloat16 g_wol[(size_t)DM * DM];

// ===========================================================================
// fp32 -> bf16 hi/lo split
// ===========================================================================
__global__ __launch_bounds__(256) void split_bf16_kernel(
    const float* __restrict__ in, __nv_bfloat16* __restrict__ hi,
    __nv_bfloat16* __restrict__ lo, int n4)
{
    int i = blockIdx.x * blockDim.x + threadIdx.x;
    if (i >= n4) return;
    float4 v = ((const float4*)in)[i];
    __nv_bfloat16 h0 = __float2bfloat16(v.x);
    __nv_bfloat16 h1 = __float2bfloat16(v.y);
    __nv_bfloat16 h2 = __float2bfloat16(v.z);
    __nv_bfloat16 h3 = __float2bfloat16(v.w);
    __nv_bfloat16 l0 = __float2bfloat16(v.x - __bfloat162float(h0));
    __nv_bfloat16 l1 = __float2bfloat16(v.y - __bfloat162float(h1));
    __nv_bfloat16 l2 = __float2bfloat16(v.z - __bfloat162float(h2));
    __nv_bfloat16 l3 = __float2bfloat16(v.w - __bfloat162float(h3));
    ushort4 H, L;
    H.x = __bfloat16_as_ushort(h0); H.y = __bfloat16_as_ushort(h1);
    H.z = __bfloat16_as_ushort(h2); H.w = __bfloat16_as_ushort(h3);
    L.x = __bfloat16_as_ushort(l0); L.y = __bfloat16_as_ushort(l1);
    L.z = __bfloat16_as_ushort(l2); L.w = __bfloat16_as_ushort(l3);
    ((ushort4*)hi)[i] = H;
    ((ushort4*)lo)[i] = L;
}

// ===========================================================================
// mma.sync bf16x3 compensated GEMM: C = A @ W^T + bias
// A: [M,K] hi/lo bf16;  W: [N,K] hi/lo bf16;  C fp32 [M,N]
// CTA 128x128, Ktile 32, 8 warps (4 m-slots x 2 n-slots), warp tile 32x64.
// mma.sync.aligned.m16n8k16.row.col.f32.bf16.bf16.f32
// Terms: Ah*Wh + Al*Wh + Ah*Wl  (Al*Wl dropped, ~2^-34 rel)
// ===========================================================================
#define SMM_STRIDE 40   // 32 k elems + 8 pad (bf16)

__device__ __forceinline__ void mma16816(
    float* d, const uint32_t* a, const uint32_t* b)
{
    asm volatile(
        "mma.sync.aligned.m16n8k16.row.col.f32.bf16.bf16.f32 "
        "{%0,%1,%2,%3}, {%4,%5,%6,%7}, {%8,%9}, {%0,%1,%2,%3};"
        : "+f"(d[0]), "+f"(d[1]), "+f"(d[2]), "+f"(d[3])
        : "r"(a[0]), "r"(a[1]), "r"(a[2]), "r"(a[3]), "r"(b[0]), "r"(b[1]));
}

__global__ __launch_bounds__(256) void mm_bf16x3_kernel(
    const __nv_bfloat16* __restrict__ Ah, const __nv_bfloat16* __restrict__ Al,
    const __nv_bfloat16* __restrict__ Wh, const __nv_bfloat16* __restrict__ Wl,
    const float* __restrict__ bias, float* __restrict__ C,
    int M, int N, int K)
{
    __shared__ uint16_t sAh[128 * SMM_STRIDE];
    __shared__ uint16_t sAl[128 * SMM_STRIDE];
    __shared__ uint16_t sWh[128 * SMM_STRIDE];
    __shared__ uint16_t sWl[128 * SMM_STRIDE];

    const int tid  = threadIdx.x;
    const int wid  = tid >> 5;
    const int lane = tid & 31;
    const int gid  = lane >> 2;       // 0..7
    const int tig  = lane & 3;        // 0..3
    const int wm   = wid & 3;         // m slot (x32 rows)
    const int wn   = wid >> 2;        // n slot (x64 cols)
    const int m0   = blockIdx.y * 128;
    const int n0   = blockIdx.x * 128;

    float acc[2][8][4];
#pragma unroll
    for (int i = 0; i < 2; i++)
#pragma unroll
        for (int j = 0; j < 8; j++)
#pragma unroll
            for (int c = 0; c < 4; c++) acc[i][j][c] = 0.f;

    for (int k0 = 0; k0 < K; k0 += 32) {
        // ---- global -> smem: each tile is 128 rows x 4 uint4 (32 bf16) ----
#pragma unroll
        for (int t = 0; t < 2; t++) {
            int idx = tid + t * 256;        // 0..511
            int row = idx >> 2;             // 0..127
            int kq  = idx & 3;              // uint4 within k tile
            uint16_t* dsta = &sAh[row * SMM_STRIDE + kq * 8];
            *(uint4*)dsta = *(const uint4*)(Ah + (size_t)(m0 + row) * K + k0 + kq * 8);
            uint16_t* dstb = &sAl[row * SMM_STRIDE + kq * 8];
            *(uint4*)dstb = *(const uint4*)(Al + (size_t)(m0 + row) * K + k0 + kq * 8);
            uint16_t* dstc = &sWh[row * SMM_STRIDE + kq * 8];
            *(uint4*)dstc = *(const uint4*)(Wh + (size_t)(n0 + row) * K + k0 + kq * 8);
            uint16_t* dstd = &sWl[row * SMM_STRIDE + kq * 8];
            *(uint4*)dstd = *(const uint4*)(Wl + (size_t)(n0 + row) * K + k0 + kq * 8);
        }
        __syncthreads();

#pragma unroll
        for (int ks = 0; ks < 2; ks++) {
            const int c = ks * 16 + tig * 2;
            uint32_t afh[2][4], afl[2][4], wf[8][2];

            // A-hi fragments (2 m-atoms)
#pragma unroll
            for (int i = 0; i < 2; i++) {
                int r = wm * 32 + i * 16 + gid;
                afh[i][0] = *(const uint32_t*)&sAh[r * SMM_STRIDE + c];
                afh[i][1] = *(const uint32_t*)&sAh[(r + 8) * SMM_STRIDE + c];
                afh[i][2] = *(const uint32_t*)&sAh[r * SMM_STRIDE + c + 8];
                afh[i][3] = *(const uint32_t*)&sAh[(r + 8) * SMM_STRIDE + c + 8];
            }
            // W-hi fragments (8 n-atoms)
#pragma unroll
            for (int j = 0; j < 8; j++) {
                int n = wn * 64 + j * 8 + gid;
                wf[j][0] = *(const uint32_t*)&sWh[n * SMM_STRIDE + c];
                wf[j][1] = *(const uint32_t*)&sWh[n * SMM_STRIDE + c + 8];
            }
            // term 1: Ah * Wh
#pragma unroll
            for (int i = 0; i < 2; i++)
#pragma unroll
                for (int j = 0; j < 8; j++) mma16816(acc[i][j], afh[i], wf[j]);

            // A-lo fragments
#pragma unroll
            for (int i = 0; i < 2; i++) {
                int r = wm * 32 + i * 16 + gid;
                afl[i][0] = *(const uint32_t*)&sAl[r * SMM_STRIDE + c];
                afl[i][1] = *(const uint32_t*)&sAl[(r + 8) * SMM_STRIDE + c];
                afl[i][2] = *(const uint32_t*)&sAl[r * SMM_STRIDE + c + 8];
                afl[i][3] = *(const uint32_t*)&sAl[(r + 8) * SMM_STRIDE + c + 8];
            }
            // term 2: Al * Wh
#pragma unroll
            for (int i = 0; i < 2; i++)
#pragma unroll
                for (int j = 0; j < 8; j++) mma16816(acc[i][j], afl[i], wf[j]);

            // W-lo fragments (overwrite wf)
#pragma unroll
            for (int j = 0; j < 8; j++) {
                int n = wn * 64 + j * 8 + gid;
                wf[j][0] = *(const uint32_t*)&sWl[n * SMM_STRIDE + c];
                wf[j][1] = *(const uint32_t*)&sWl[n * SMM_STRIDE + c + 8];
            }
            // term 3: Ah * Wl
#pragma unroll
            for (int i = 0; i < 2; i++)
#pragma unroll
                for (int j = 0; j < 8; j++) mma16816(acc[i][j], afh[i], wf[j]);
        }
        __syncthreads();
    }

    // ---- epilogue: bias add + store ----
#pragma unroll
    for (int i = 0; i < 2; i++) {
        int row = m0 + wm * 32 + i * 16 + gid;
#pragma unroll
        for (int j = 0; j < 8; j++) {
            int col = n0 + wn * 64 + j * 8 + tig * 2;
            float b0 = bias[col], b1 = bias[col + 1];
            float2 v0 = make_float2(acc[i][j][0] + b0, acc[i][j][1] + b1);
            float2 v1 = make_float2(acc[i][j][2] + b0, acc[i][j][3] + b1);
            *(float2*)(C + (size_t)row * N + col) = v0;
            *(float2*)(C + (size_t)(row + 8) * N + col) = v1;
        }
    }
}

// ===========================================================================
// Scores: s[b,h,qi,j] = (q_row . k_row) / 8     (fp32, unchanged)
// ===========================================================================
__global__ __launch_bounds__(256) void scores_kernel(
    const float* __restrict__ q, const float* __restrict__ k,
    float* __restrict__ s)
{
    __shared__ float Qs[64][128];
    __shared__ float Ks[64][64];

    const int bh = blockIdx.z;
    const int b  = bh >> 4;
    const int h  = bh & 15;
    const int q0 = blockIdx.y * 128;
    const int j0 = blockIdx.x * 64;
    const int tid = threadIdx.x;

    const float* qb = q + ((size_t)(b * SEQ + q0)) * DM + h * HDIM;
    const float* kb = k + ((size_t)(b * SEQ + j0)) * DM + h * HDIM;

#pragma unroll
    for (int i = 0; i < 8; i++) {
        int idx = tid + i * 256;
        int row = idx & 127;
        int kg  = idx >> 7;
        float4 v4 = *(const float4*)(qb + (size_t)row * DM + kg * 4);
        Qs[kg * 4 + 0][row] = v4.x; Qs[kg * 4 + 1][row] = v4.y;
        Qs[kg * 4 + 2][row] = v4.z; Qs[kg * 4 + 3][row] = v4.w;
    }
#pragma unroll
    for (int i = 0; i < 4; i++) {
        int idx = tid + i * 256;
        int row = idx & 63;
        int kg  = idx >> 6;
        float4 v4 = *(const float4*)(kb + (size_t)row * DM + kg * 4);
        Ks[kg * 4 + 0][row] = v4.x; Ks[kg * 4 + 1][row] = v4.y;
        Ks[kg * 4 + 2][row] = v4.z; Ks[kg * 4 + 3][row] = v4.w;
    }
    __syncthreads();

    const int ty = tid >> 4;
    const int tx = tid & 15;
    float acc[8][4];
#pragma unroll
    for (int i = 0; i < 8; i++)
#pragma unroll
        for (int j = 0; j < 4; j++) acc[i][j] = 0.f;

#pragma unroll 8
    for (int kk = 0; kk < 64; kk++) {
        float a[8], bb[4];
        *(float4*)(a)     = *(const float4*)&Qs[kk][ty * 8];
        *(float4*)(a + 4) = *(const float4*)&Qs[kk][ty * 8 + 4];
        *(float4*)(bb)    = *(const float4*)&Ks[kk][tx * 4];
#pragma unroll
        for (int i = 0; i < 8; i++)
#pragma unroll
            for (int j = 0; j < 4; j++) acc[i][j] += a[i] * bb[j];
    }

    float* outp = s + ((size_t)bh * SEQ + q0) * SEQ + j0;
#pragma unroll
    for (int i = 0; i < 8; i++) {
        int row = ty * 8 + i;
        float4 o;
        o.x = acc[i][0] * 0.125f;
        o.y = acc[i][1] * 0.125f;
        o.z = acc[i][2] * 0.125f;
        o.w = acc[i][3] * 0.125f;
        *(float4*)(outp + (size_t)row * SEQ + tx * 4) = o;
    }
}

// ===========================================================================
// Softmax over j (+mask), NaN->0, sum over batch (unchanged)
// ===========================================================================
__global__ __launch_bounds__(256) void softmax_sum_kernel(
    const float* __restrict__ s, const float* __restrict__ mask,
    float* __restrict__ att)
{
    __shared__ float red[8];

    const int h   = blockIdx.x >> 10;
    const int qi  = blockIdx.x & 1023;
    const int tid = threadIdx.x;
    const int lane = tid & 31;
    const int warp = tid >> 5;

    float mv[4];
#pragma unroll
    for (int u = 0; u < 4; u++) mv[u] = mask[(size_t)qi * SEQ + tid + u * 256];

    float facc[4] = {0.f, 0.f, 0.f, 0.f};

    for (int b = 0; b < NB; b++) {
        const float* srow = s + (((size_t)(b * NHEAD + h)) * SEQ + qi) * SEQ;
        float rv[4];
        float m = -INFINITY;
#pragma unroll
        for (int u = 0; u < 4; u++) {
            rv[u] = srow[tid + u * 256] + mv[u];
            m = fmaxf(m, rv[u]);
        }
#pragma unroll
        for (int o = 16; o > 0; o >>= 1) m = fmaxf(m, __shfl_xor_sync(0xffffffffu, m, o));
        __syncthreads();
        if (lane == 0) red[warp] = m;
        __syncthreads();
        m = red[0];
#pragma unroll
        for (int w = 1; w < 8; w++) m = fmaxf(m, red[w]);

        float ssum = 0.f;
#pragma unroll
        for (int u = 0; u < 4; u++) {
            rv[u] = __expf(rv[u] - m);
            ssum += rv[u];
        }
#pragma unroll
        for (int o = 16; o > 0; o >>= 1) ssum += __shfl_xor_sync(0xffffffffu, ssum, o);
        __syncthreads();
        if (lane == 0) red[warp] = ssum;
        __syncthreads();
        ssum = 0.f;
#pragma unroll
        for (int w = 0; w < 8; w++) ssum += red[w];

        if (ssum > 0.f && isfinite(ssum)) {
            float inv = 1.f / ssum;
#pragma unroll
            for (int u = 0; u < 4; u++) facc[u] += rv[u] * inv;
        }
    }

    float* arow = att + ((size_t)h * SEQ + qi) * SEQ;
#pragma unroll
    for (int u = 0; u < 4; u++) arow[tid + u * 256] = facc[u];
}

// ===========================================================================
// AV: out[b, m, h*64+d] = sum_j att[h,m,j] * v[b, j, h*64+d]  (unchanged)
// ===========================================================================
__global__ __launch_bounds__(256) void av_kernel(
    const float* __restrict__ att, const float* __restrict__ v,
    float* __restrict__ out)
{
    __shared__ float As[16][128];
    __shared__ float Vs[16][64];

    const int bh = blockIdx.y;
    const int b  = bh >> 4;
    const int h  = bh & 15;
    const int m0 = blockIdx.x * 128;
    const int tid = threadIdx.x;
    const int ty = tid >> 4;
    const int tx = tid & 15;

    const float* ab = att + ((size_t)h * SEQ + m0) * SEQ;
    const float* vb = v + (size_t)b * SEQ * DM + h * HDIM;

    float acc[8][4];
#pragma unroll
    for (int i = 0; i < 8; i++)
#pragma unroll
        for (int j = 0; j < 4; j++) acc[i][j] = 0.f;

    for (int k0 = 0; k0 < SEQ; k0 += 16) {
#pragma unroll
        for (int i = 0; i < 2; i++) {
            int idx = tid + i * 256;
            int row = idx & 127;
            int kg  = idx >> 7;
            float4 a4 = *(const float4*)(ab + (size_t)row * SEQ + k0 + kg * 4);
            As[kg * 4 + 0][row] = a4.x; As[kg * 4 + 1][row] = a4.y;
            As[kg * 4 + 2][row] = a4.z; As[kg * 4 + 3][row] = a4.w;
        }
        {
            int vr = tid >> 4;
            int vc = (tid & 15) << 2;
            float4 v4 = *(const float4*)(vb + (size_t)(k0 + vr) * DM + vc);
            Vs[vr][vc + 0] = v4.x; Vs[vr][vc + 1] = v4.y;
            Vs[vr][vc + 2] = v4.z; Vs[vr][vc + 3] = v4.w;
        }
        __syncthreads();

#pragma unroll
        for (int kk = 0; kk < 16; kk++) {
            float a[8], bb[4];
            *(float4*)(a)     = *(const float4*)&As[kk][ty * 8];
            *(float4*)(a + 4) = *(const float4*)&As[kk][ty * 8 + 4];
            *(float4*)(bb)    = *(const float4*)&Vs[kk][tx * 4];
#pragma unroll
            for (int i = 0; i < 8; i++)
#pragma unroll
                for (int j = 0; j < 4; j++) acc[i][j] += a[i] * bb[j];
        }
        __syncthreads();
    }

    float* ob = out + ((size_t)(b * SEQ + m0)) * DM + h * HDIM;
#pragma unroll
    for (int i = 0; i < 8; i++) {
        float4 o;
        o.x = acc[i][0]; o.y = acc[i][1]; o.z = acc[i][2]; o.w = acc[i][3];
        *(float4*)(ob + (size_t)(ty * 8 + i) * DM + tx * 4) = o;
    }
}

// ===========================================================================
extern "C" void kernel_launch(void* const* d_in, const int* in_sizes, int n_in,
                              void* d_out, int out_size)
{
    const float* x    = (const float*)d_in[0];
    const float* y    = (const float*)d_in[1];
    const float* mask = (const float*)d_in[2];
    const float* Wq   = (const float*)d_in[3];
    const float* bq   = (const float*)d_in[4];
    const float* Wk   = (const float*)d_in[5];
    const float* bk   = (const float*)d_in[6];
    const float* Wv   = (const float*)d_in[7];
    const float* bv   = (const float*)d_in[8];
    const float* Wo   = (const float*)d_in[9];
    const float* bo   = (const float*)d_in[10];
    float* out = (float*)d_out;

    float *q, *k, *v, *sc, *att, *av;
    cudaGetSymbolAddress((void**)&q,   g_q);
    cudaGetSymbolAddress((void**)&k,   g_k);
    cudaGetSymbolAddress((void**)&v,   g_v);
    cudaGetSymbolAddress((void**)&sc,  g_s);
    cudaGetSymbolAddress((void**)&att, g_att);
    cudaGetSymbolAddress((void**)&av,  g_av);

    __nv_bfloat16 *yh, *yl, *xh, *xl, *avh, *avl;
    __nv_bfloat16 *wqh, *wql, *wkh, *wkl, *wvh, *wvl, *woh, *wol;
    cudaGetSymbolAddress((void**)&yh, g_yh);   cudaGetSymbolAddress((void**)&yl, g_yl);
    cudaGetSymbolAddress((void**)&xh, g_xh);   cudaGetSymbolAddress((void**)&xl, g_xl);
    cudaGetSymbolAddress((void**)&avh, g_avh); cudaGetSymbolAddress((void**)&avl, g_avl);
    cudaGetSymbolAddress((void**)&wqh, g_wqh); cudaGetSymbolAddress((void**)&wql, g_wql);
    cudaGetSymbolAddress((void**)&wkh, g_wkh); cudaGetSymbolAddress((void**)&wkl, g_wkl);
    cudaGetSymbolAddress((void**)&wvh, g_wvh); cudaGetSymbolAddress((void**)&wvl, g_wvl);
    cudaGetSymbolAddress((void**)&woh, g_woh); cudaGetSymbolAddress((void**)&wol, g_wol);

    const int n4_act = MR * DM / 4;   // 1,048,576
    const int n4_w   = DM * DM / 4;   // 262,144

    // ---- bf16 hi/lo splits ----
    split_bf16_kernel<<<n4_act / 256, 256>>>(y, yh, yl, n4_act);
    split_bf16_kernel<<<n4_act / 256, 256>>>(x, xh, xl, n4_act);
    split_bf16_kernel<<<n4_w / 256, 256>>>(Wq, wqh, wql, n4_w);
    split_bf16_kernel<<<n4_w / 256, 256>>>(Wk, wkh, wkl, n4_w);
    split_bf16_kernel<<<n4_w / 256, 256>>>(Wv, wvh, wvl, n4_w);
    split_bf16_kernel<<<n4_w / 256, 256>>>(Wo, woh, wol, n4_w);

    // ---- projections on tensor cores (mma.sync bf16x3) ----
    dim3 mmgrid(DM / 128, MR / 128);  // (8, 32)
    mm_bf16x3_kernel<<<mmgrid, 256>>>(yh, yl, wqh, wql, bq, q, MR, DM, DM);
    mm_bf16x3_kernel<<<mmgrid, 256>>>(xh, xl, wkh, wkl, bk, k, MR, DM, DM);
    mm_bf16x3_kernel<<<mmgrid, 256>>>(xh, xl, wvh, wvl, bv, v, MR, DM, DM);

    // ---- attention (fp32 path) ----
    scores_kernel<<<dim3(SEQ / 64, SEQ / 128, NB * NHEAD), 256>>>(q, k, sc);
    softmax_sum_kernel<<<NHEAD * SEQ, 256>>>(sc, mask, att);
    av_kernel<<<dim3(SEQ / 128, NB * NHEAD), 256>>>(att, v, av);

    // ---- output projection on tensor cores ----
    split_bf16_kernel<<<n4_act / 256, 256>>>(av, avh, avl, n4_act);
    mm_bf16x3_kernel<<<mmgrid, 256>>>(avh, avl, woh, wol, bo, out, MR, DM, DM);
}

// round 6
// speedup vs baseline: 1.9732x; 1.3625x over previous
#include <cuda_runtime.h>
#include <cuda_bf16.h>
#include <math.h>
#include <stdint.h>

// Problem constants
constexpr int SEQ   = 1024;
constexpr int DM    = 1024;
constexpr int NHEAD = 16;
constexpr int HDIM  = 64;
constexpr int NB    = 4;
constexpr int MR    = NB * SEQ;   // 4096 rows for the big GEMMs

// ---------------- scratch (device globals; no allocation allowed) ----------
__device__ float g_q [(size_t)MR * DM];
__device__ float g_k [(size_t)MR * DM];
__device__ float g_v [(size_t)MR * DM];
__device__ float g_s [(size_t)NB * NHEAD * SEQ * SEQ];   // raw scores (b,h,q,j)
__device__ float g_av[(size_t)MR * DM];                  // attention output pre-proj

// bf16 hi/lo splits
__device__ __nv_bfloat16 g_yh[(size_t)MR * DM];
__device__ __nv_bfloat16 g_yl[(size_t)MR * DM];
__device__ __nv_bfloat16 g_xh[(size_t)MR * DM];
__device__ __nv_bfloat16 g_xl[(size_t)MR * DM];
__device__ __nv_bfloat16 g_avh[(size_t)MR * DM];
__device__ __nv_bfloat16 g_avl[(size_t)MR * DM];
__device__ __nv_bfloat16 g_qh[(size_t)MR * DM];
__device__ __nv_bfloat16 g_ql[(size_t)MR * DM];
__device__ __nv_bfloat16 g_kh[(size_t)MR * DM];
__device__ __nv_bfloat16 g_kl[(size_t)MR * DM];
__device__ __nv_bfloat16 g_vth[(size_t)MR * DM];   // v^T per (b,h): [b][h][d][j]
__device__ __nv_bfloat16 g_vtl[(size_t)MR * DM];
__device__ __nv_bfloat16 g_atth[(size_t)NHEAD * SEQ * SEQ];
__device__ __nv_bfloat16 g_attl[(size_t)NHEAD * SEQ * SEQ];
__device__ __nv_bfloat16 g_wqh[(size_t)DM * DM];
__device__ __nv_bfloat16 g_wql[(size_t)DM * DM];
__device__ __nv_bfloat16 g_wkh[(size_t)DM * DM];
__device__ __nv_bfloat16 g_wkl[(size_t)DM * DM];
__device__ __nv_bfloat16 g_wvh[(size_t)DM * DM];
__device__ __nv_bfloat16 g_wvl[(size_t)DM * DM];
__device__ __nv_bfloat16 g_woh[(size_t)DM * DM];
__device__ __nv_bfloat16 g_wol[(size_t)DM * DM];

// ===========================================================================
// helpers
// ===========================================================================
__device__ __forceinline__ uint32_t smem_u32(const void* p) {
    uint32_t r;
    asm("{ .reg .u64 t; cvta.to.shared.u64 t, %1; cvt.u32.u64 %0, t; }"
        : "=r"(r) : "l"(p));
    return r;
}
__device__ __forceinline__ void cp16(uint32_t dst, const void* src) {
    asm volatile("cp.async.cg.shared.global [%0], [%1], 16;" :: "r"(dst), "l"(src));
}
__device__ __forceinline__ void cp_commit() {
    asm volatile("cp.async.commit_group;" ::: "memory");
}
template <int N>
__device__ __forceinline__ void cp_wait() {
    asm volatile("cp.async.wait_group %0;" :: "n"(N) : "memory");
}

__device__ __forceinline__ void mma16816(
    float* d, const uint32_t* a, const uint32_t* b)
{
    asm volatile(
        "mma.sync.aligned.m16n8k16.row.col.f32.bf16.bf16.f32 "
        "{%0,%1,%2,%3}, {%4,%5,%6,%7}, {%8,%9}, {%0,%1,%2,%3};"
        : "+f"(d[0]), "+f"(d[1]), "+f"(d[2]), "+f"(d[3])
        : "r"(a[0]), "r"(a[1]), "r"(a[2]), "r"(a[3]), "r"(b[0]), "r"(b[1]));
}

// ===========================================================================
// fp32 -> bf16 hi/lo split
// ===========================================================================
__global__ __launch_bounds__(256) void split_bf16_kernel(
    const float* __restrict__ in, __nv_bfloat16* __restrict__ hi,
    __nv_bfloat16* __restrict__ lo, int n4)
{
    int i = blockIdx.x * blockDim.x + threadIdx.x;
    if (i >= n4) return;
    float4 v = ((const float4*)in)[i];
    __nv_bfloat16 h0 = __float2bfloat16(v.x);
    __nv_bfloat16 h1 = __float2bfloat16(v.y);
    __nv_bfloat16 h2 = __float2bfloat16(v.z);
    __nv_bfloat16 h3 = __float2bfloat16(v.w);
    __nv_bfloat16 l0 = __float2bfloat16(v.x - __bfloat162float(h0));
    __nv_bfloat16 l1 = __float2bfloat16(v.y - __bfloat162float(h1));
    __nv_bfloat16 l2 = __float2bfloat16(v.z - __bfloat162float(h2));
    __nv_bfloat16 l3 = __float2bfloat16(v.w - __bfloat162float(h3));
    ushort4 H, L;
    H.x = __bfloat16_as_ushort(h0); H.y = __bfloat16_as_ushort(h1);
    H.z = __bfloat16_as_ushort(h2); H.w = __bfloat16_as_ushort(h3);
    L.x = __bfloat16_as_ushort(l0); L.y = __bfloat16_as_ushort(l1);
    L.z = __bfloat16_as_ushort(l2); L.w = __bfloat16_as_ushort(l3);
    ((ushort4*)hi)[i] = H;
    ((ushort4*)lo)[i] = L;
}

// ===========================================================================
// transpose + hi/lo split of v:  vt[b][h][d][j] = v[b*S+j][h*64+d]
// grid: (S/64 jtiles, NB*NHEAD), 256 threads
// ===========================================================================
__global__ __launch_bounds__(256) void transpose_split_v_kernel(
    const float* __restrict__ v, __nv_bfloat16* __restrict__ vth,
    __nv_bfloat16* __restrict__ vtl)
{
    __shared__ float t[64][65];
    const int bh = blockIdx.y;
    const int b  = bh >> 4;
    const int h  = bh & 15;
    const int j0 = blockIdx.x * 64;
    const int tid = threadIdx.x;

    // load 64 j-rows x 64 d, store transposed into smem
#pragma unroll
    for (int i = 0; i < 4; i++) {
        int idx = tid + i * 256;          // 0..1023
        int j   = idx >> 4;               // 0..63
        int dq  = (idx & 15) * 4;         // 0..60
        float4 v4 = *(const float4*)(v + (size_t)(b * SEQ + j0 + j) * DM + h * HDIM + dq);
        t[dq + 0][j] = v4.x; t[dq + 1][j] = v4.y;
        t[dq + 2][j] = v4.z; t[dq + 3][j] = v4.w;
    }
    __syncthreads();

    const int d  = tid >> 2;              // 0..63
    const int jq = (tid & 3) * 16;        // 0..48
    __nv_bfloat16* oh = vth + ((size_t)bh * HDIM + d) * SEQ + j0 + jq;
    __nv_bfloat16* ol = vtl + ((size_t)bh * HDIM + d) * SEQ + j0 + jq;
#pragma unroll
    for (int c = 0; c < 4; c++) {
        ushort4 H, L;
        float f0 = t[d][jq + c * 4 + 0];
        float f1 = t[d][jq + c * 4 + 1];
        float f2 = t[d][jq + c * 4 + 2];
        float f3 = t[d][jq + c * 4 + 3];
        __nv_bfloat16 h0 = __float2bfloat16(f0), h1 = __float2bfloat16(f1);
        __nv_bfloat16 h2 = __float2bfloat16(f2), h3 = __float2bfloat16(f3);
        H.x = __bfloat16_as_ushort(h0); H.y = __bfloat16_as_ushort(h1);
        H.z = __bfloat16_as_ushort(h2); H.w = __bfloat16_as_ushort(h3);
        L.x = __bfloat16_as_ushort(__float2bfloat16(f0 - __bfloat162float(h0)));
        L.y = __bfloat16_as_ushort(__float2bfloat16(f1 - __bfloat162float(h1)));
        L.z = __bfloat16_as_ushort(__float2bfloat16(f2 - __bfloat162float(h2)));
        L.w = __bfloat16_as_ushort(__float2bfloat16(f3 - __bfloat162float(h3)));
        *(ushort4*)(oh + c * 4) = H;
        *(ushort4*)(ol + c * 4) = L;
    }
}

// ===========================================================================
// Generic bf16x3 compensated GEMM on mma.sync with cp.async double buffering.
//   C = scale * (A @ W^T) (+ bias)
// A: [M,K] hi/lo bf16, row stride lda;  W: [N,K] hi/lo, row stride ldw.
// Per blockIdx.z: zb=z>>4, zh=z&15; operand offset = zb*sb + zh*sh.
// NT = CTA n-tile (128 or 64). CTA m-tile 128, Ktile 32, 8 warps.
// ===========================================================================
#define SMM_STRIDE 40   // 32 k elems + 8 pad (bf16)

template <int NT>
__global__ __launch_bounds__(256) void mm3_kernel(
    const __nv_bfloat16* __restrict__ Ah, const __nv_bfloat16* __restrict__ Al,
    size_t asb, size_t ash, int lda,
    const __nv_bfloat16* __restrict__ Wh, const __nv_bfloat16* __restrict__ Wl,
    size_t wsb, size_t wsh, int ldw,
    const float* __restrict__ bias, float* __restrict__ C,
    size_t csb, size_t csh, int ldc,
    int K, float scale)
{
    constexpr int NATOMS = NT / 16;                 // n-atoms per warp
    constexpr int A_BYTES = 128 * SMM_STRIDE * 2;   // 10240
    constexpr int W_BYTES = NT * SMM_STRIDE * 2;
    constexpr int STAGE   = 2 * A_BYTES + 2 * W_BYTES;

    extern __shared__ char smem[];
    const uint32_t sbase = smem_u32(smem);

    const int tid  = threadIdx.x;
    const int wid  = tid >> 5;
    const int lane = tid & 31;
    const int gid  = lane >> 2;
    const int tig  = lane & 3;
    const int wm   = wid & 3;
    const int wn   = wid >> 2;
    const int m0   = blockIdx.y * 128;
    const int n0   = blockIdx.x * NT;
    const int z    = blockIdx.z;
    const int zb   = z >> 4;
    const int zh   = z & 15;

    const __nv_bfloat16* pAh = Ah + (size_t)zb * asb + (size_t)zh * ash;
    const __nv_bfloat16* pAl = Al + (size_t)zb * asb + (size_t)zh * ash;
    const __nv_bfloat16* pWh = Wh + (size_t)zb * wsb + (size_t)zh * wsh;
    const __nv_bfloat16* pWl = Wl + (size_t)zb * wsb + (size_t)zh * wsh;

    float acc[2][NATOMS][4];
#pragma unroll
    for (int i = 0; i < 2; i++)
#pragma unroll
        for (int j = 0; j < NATOMS; j++)
#pragma unroll
            for (int c = 0; c < 4; c++) acc[i][j][c] = 0.f;

    const int nk = K >> 5;

    // ---- stage loader (cp.async, 16B chunks) ----
    auto load_stage = [&](int s, int k0) {
        uint32_t st = sbase + s * STAGE;
#pragma unroll
        for (int i = 0; i < 2; i++) {
            int idx = tid + i * 256;          // 0..511
            int row = idx >> 2;               // 0..127
            int kq  = idx & 3;
            uint32_t doff = (row * SMM_STRIDE + kq * 8) * 2;
            cp16(st + doff,           pAh + (size_t)(m0 + row) * lda + k0 + kq * 8);
            cp16(st + A_BYTES + doff, pAl + (size_t)(m0 + row) * lda + k0 + kq * 8);
        }
#pragma unroll
        for (int i = 0; i < (NT == 128 ? 2 : 1); i++) {
            int idx = tid + i * 256;
            int row = idx >> 2;
            int kq  = idx & 3;
            uint32_t doff = (row * SMM_STRIDE + kq * 8) * 2;
            cp16(st + 2 * A_BYTES + doff,           pWh + (size_t)(n0 + row) * ldw + k0 + kq * 8);
            cp16(st + 2 * A_BYTES + W_BYTES + doff, pWl + (size_t)(n0 + row) * ldw + k0 + kq * 8);
        }
    };

    load_stage(0, 0);
    cp_commit();

    for (int c0 = 0; c0 < nk; c0++) {
        if (c0 + 1 < nk) { load_stage((c0 + 1) & 1, (c0 + 1) * 32); cp_commit(); }
        if (c0 + 1 < nk) cp_wait<1>(); else cp_wait<0>();
        __syncthreads();

        const char* st = smem + (c0 & 1) * STAGE;
        const uint16_t* sAh = (const uint16_t*)(st);
        const uint16_t* sAl = (const uint16_t*)(st + A_BYTES);
        const uint16_t* sWh = (const uint16_t*)(st + 2 * A_BYTES);
        const uint16_t* sWl = (const uint16_t*)(st + 2 * A_BYTES + W_BYTES);

#pragma unroll
        for (int ks = 0; ks < 2; ks++) {
            const int c = ks * 16 + tig * 2;
            uint32_t afh[2][4], afl[2][4], wf[NATOMS][2];

#pragma unroll
            for (int i = 0; i < 2; i++) {
                int r = wm * 32 + i * 16 + gid;
                afh[i][0] = *(const uint32_t*)&sAh[r * SMM_STRIDE + c];
                afh[i][1] = *(const uint32_t*)&sAh[(r + 8) * SMM_STRIDE + c];
                afh[i][2] = *(const uint32_t*)&sAh[r * SMM_STRIDE + c + 8];
                afh[i][3] = *(const uint32_t*)&sAh[(r + 8) * SMM_STRIDE + c + 8];
            }
#pragma unroll
            for (int j = 0; j < NATOMS; j++) {
                int n = wn * (NT / 2) + j * 8 + gid;
                wf[j][0] = *(const uint32_t*)&sWh[n * SMM_STRIDE + c];
                wf[j][1] = *(const uint32_t*)&sWh[n * SMM_STRIDE + c + 8];
            }
#pragma unroll
            for (int i = 0; i < 2; i++)
#pragma unroll
                for (int j = 0; j < NATOMS; j++) mma16816(acc[i][j], afh[i], wf[j]);

#pragma unroll
            for (int i = 0; i < 2; i++) {
                int r = wm * 32 + i * 16 + gid;
                afl[i][0] = *(const uint32_t*)&sAl[r * SMM_STRIDE + c];
                afl[i][1] = *(const uint32_t*)&sAl[(r + 8) * SMM_STRIDE + c];
                afl[i][2] = *(const uint32_t*)&sAl[r * SMM_STRIDE + c + 8];
                afl[i][3] = *(const uint32_t*)&sAl[(r + 8) * SMM_STRIDE + c + 8];
            }
#pragma unroll
            for (int i = 0; i < 2; i++)
#pragma unroll
                for (int j = 0; j < NATOMS; j++) mma16816(acc[i][j], afl[i], wf[j]);

#pragma unroll
            for (int j = 0; j < NATOMS; j++) {
                int n = wn * (NT / 2) + j * 8 + gid;
                wf[j][0] = *(const uint32_t*)&sWl[n * SMM_STRIDE + c];
                wf[j][1] = *(const uint32_t*)&sWl[n * SMM_STRIDE + c + 8];
            }
#pragma unroll
            for (int i = 0; i < 2; i++)
#pragma unroll
                for (int j = 0; j < NATOMS; j++) mma16816(acc[i][j], afh[i], wf[j]);
        }
        __syncthreads();
    }

    // ---- epilogue ----
    float* pC = C + (size_t)zb * csb + (size_t)zh * csh;
#pragma unroll
    for (int i = 0; i < 2; i++) {
        int row = m0 + wm * 32 + i * 16 + gid;
#pragma unroll
        for (int j = 0; j < NATOMS; j++) {
            int col = n0 + wn * (NT / 2) + j * 8 + tig * 2;
            float b0 = bias ? bias[col] : 0.f;
            float b1 = bias ? bias[col + 1] : 0.f;
            float2 v0 = make_float2(acc[i][j][0] * scale + b0, acc[i][j][1] * scale + b1);
            float2 v1 = make_float2(acc[i][j][2] * scale + b0, acc[i][j][3] * scale + b1);
            *(float2*)(pC + (size_t)row * ldc + col) = v0;
            *(float2*)(pC + (size_t)(row + 8) * ldc + col) = v1;
        }
    }
}

// ===========================================================================
// Softmax over j (+mask), NaN->0, sum over batch; emits bf16 hi/lo att.
// ===========================================================================
__global__ __launch_bounds__(256) void softmax_sum_kernel(
    const float* __restrict__ s, const float* __restrict__ mask,
    __nv_bfloat16* __restrict__ atth, __nv_bfloat16* __restrict__ attl)
{
    __shared__ float red[8];

    const int h   = blockIdx.x >> 10;
    const int qi  = blockIdx.x & 1023;
    const int tid = threadIdx.x;
    const int lane = tid & 31;
    const int warp = tid >> 5;

    float mv[4];
#pragma unroll
    for (int u = 0; u < 4; u++) mv[u] = mask[(size_t)qi * SEQ + tid + u * 256];

    float facc[4] = {0.f, 0.f, 0.f, 0.f};

    for (int b = 0; b < NB; b++) {
        const float* srow = s + (((size_t)(b * NHEAD + h)) * SEQ + qi) * SEQ;
        float rv[4];
        float m = -INFINITY;
#pragma unroll
        for (int u = 0; u < 4; u++) {
            rv[u] = srow[tid + u * 256] + mv[u];
            m = fmaxf(m, rv[u]);
        }
#pragma unroll
        for (int o = 16; o > 0; o >>= 1) m = fmaxf(m, __shfl_xor_sync(0xffffffffu, m, o));
        __syncthreads();
        if (lane == 0) red[warp] = m;
        __syncthreads();
        m = red[0];
#pragma unroll
        for (int w = 1; w < 8; w++) m = fmaxf(m, red[w]);

        float ssum = 0.f;
#pragma unroll
        for (int u = 0; u < 4; u++) {
            rv[u] = __expf(rv[u] - m);
            ssum += rv[u];
        }
#pragma unroll
        for (int o = 16; o > 0; o >>= 1) ssum += __shfl_xor_sync(0xffffffffu, ssum, o);
        __syncthreads();
        if (lane == 0) red[warp] = ssum;
        __syncthreads();
        ssum = 0.f;
#pragma unroll
        for (int w = 0; w < 8; w++) ssum += red[w];

        if (ssum > 0.f && isfinite(ssum)) {
            float inv = 1.f / ssum;
#pragma unroll
            for (int u = 0; u < 4; u++) facc[u] += rv[u] * inv;
        }
    }

    size_t rowoff = ((size_t)h * SEQ + qi) * SEQ;
#pragma unroll
    for (int u = 0; u < 4; u++) {
        float f = facc[u];
        __nv_bfloat16 hi = __float2bfloat16(f);
        atth[rowoff + tid + u * 256] = hi;
        attl[rowoff + tid + u * 256] = __float2bfloat16(f - __bfloat162float(hi));
    }
}

// ===========================================================================
extern "C" void kernel_launch(void* const* d_in, const int* in_sizes, int n_in,
                              void* d_out, int out_size)
{
    const float* x    = (const float*)d_in[0];
    const float* y    = (const float*)d_in[1];
    const float* mask = (const float*)d_in[2];
    const float* Wq   = (const float*)d_in[3];
    const float* bq   = (const float*)d_in[4];
    const float* Wk   = (const float*)d_in[5];
    const float* bk   = (const float*)d_in[6];
    const float* Wv   = (const float*)d_in[7];
    const float* bv   = (const float*)d_in[8];
    const float* Wo   = (const float*)d_in[9];
    const float* bo   = (const float*)d_in[10];
    float* out = (float*)d_out;

    float *q, *k, *v, *sc, *av;
    cudaGetSymbolAddress((void**)&q,  g_q);
    cudaGetSymbolAddress((void**)&k,  g_k);
    cudaGetSymbolAddress((void**)&v,  g_v);
    cudaGetSymbolAddress((void**)&sc, g_s);
    cudaGetSymbolAddress((void**)&av, g_av);

    __nv_bfloat16 *yh, *yl, *xh, *xl, *avh, *avl;
    __nv_bfloat16 *qh, *ql, *kh, *kl, *vth, *vtl, *atth, *attl;
    __nv_bfloat16 *wqh, *wql, *wkh, *wkl, *wvh, *wvl, *woh, *wol;
    cudaGetSymbolAddress((void**)&yh, g_yh);   cudaGetSymbolAddress((void**)&yl, g_yl);
    cudaGetSymbolAddress((void**)&xh, g_xh);   cudaGetSymbolAddress((void**)&xl, g_xl);
    cudaGetSymbolAddress((void**)&avh, g_avh); cudaGetSymbolAddress((void**)&avl, g_avl);
    cudaGetSymbolAddress((void**)&qh, g_qh);   cudaGetSymbolAddress((void**)&ql, g_ql);
    cudaGetSymbolAddress((void**)&kh, g_kh);   cudaGetSymbolAddress((void**)&kl, g_kl);
    cudaGetSymbolAddress((void**)&vth, g_vth); cudaGetSymbolAddress((void**)&vtl, g_vtl);
    cudaGetSymbolAddress((void**)&atth, g_atth); cudaGetSymbolAddress((void**)&attl, g_attl);
    cudaGetSymbolAddress((void**)&wqh, g_wqh); cudaGetSymbolAddress((void**)&wql, g_wql);
    cudaGetSymbolAddress((void**)&wkh, g_wkh); cudaGetSymbolAddress((void**)&wkl, g_wkl);
    cudaGetSymbolAddress((void**)&wvh, g_wvh); cudaGetSymbolAddress((void**)&wvl, g_wvl);
    cudaGetSymbolAddress((void**)&woh, g_woh); cudaGetSymbolAddress((void**)&wol, g_wol);

    constexpr int SMEM128 = 2 * (2 * 128 * SMM_STRIDE * 2 + 2 * 128 * SMM_STRIDE * 2); // 81920
    constexpr int SMEM64  = 2 * (2 * 128 * SMM_STRIDE * 2 + 2 * 64 * SMM_STRIDE * 2);  // 61440
    cudaFuncSetAttribute(mm3_kernel<128>, cudaFuncAttributeMaxDynamicSharedMemorySize, SMEM128);
    cudaFuncSetAttribute(mm3_kernel<64>,  cudaFuncAttributeMaxDynamicSharedMemorySize, SMEM64);

    const int n4_act = MR * DM / 4;
    const int n4_w   = DM * DM / 4;
    const size_t SDM = (size_t)SEQ * DM;
    const size_t SS  = (size_t)SEQ * SEQ;

    // ---- input splits ----
    split_bf16_kernel<<<n4_act / 256, 256>>>(y, yh, yl, n4_act);
    split_bf16_kernel<<<n4_act / 256, 256>>>(x, xh, xl, n4_act);
    split_bf16_kernel<<<n4_w / 256, 256>>>(Wq, wqh, wql, n4_w);
    split_bf16_kernel<<<n4_w / 256, 256>>>(Wk, wkh, wkl, n4_w);
    split_bf16_kernel<<<n4_w / 256, 256>>>(Wv, wvh, wvl, n4_w);
    split_bf16_kernel<<<n4_w / 256, 256>>>(Wo, woh, wol, n4_w);

    // ---- projections: C = A @ W^T + bias ----
    dim3 pgrid(DM / 128, MR / 128, 1);
    mm3_kernel<128><<<pgrid, 256, SMEM128>>>(yh, yl, 0, 0, DM, wqh, wql, 0, 0, DM,
                                             bq, q, 0, 0, DM, DM, 1.f);
    mm3_kernel<128><<<pgrid, 256, SMEM128>>>(xh, xl, 0, 0, DM, wkh, wkl, 0, 0, DM,
                                             bk, k, 0, 0, DM, DM, 1.f);
    mm3_kernel<128><<<pgrid, 256, SMEM128>>>(xh, xl, 0, 0, DM, wvh, wvl, 0, 0, DM,
                                             bv, v, 0, 0, DM, DM, 1.f);

    // ---- splits of q, k; transposed split of v ----
    split_bf16_kernel<<<n4_act / 256, 256>>>(q, qh, ql, n4_act);
    split_bf16_kernel<<<n4_act / 256, 256>>>(k, kh, kl, n4_act);
    transpose_split_v_kernel<<<dim3(SEQ / 64, NB * NHEAD), 256>>>(v, vth, vtl);

    // ---- scores: s[b,h] = 0.125 * q_bh @ k_bh^T  (K=64) ----
    mm3_kernel<128><<<dim3(SEQ / 128, SEQ / 128, NB * NHEAD), 256, SMEM128>>>(
        qh, ql, SDM, (size_t)HDIM, DM,
        kh, kl, SDM, (size_t)HDIM, DM,
        nullptr, sc, (size_t)NHEAD * SS, SS, SEQ, HDIM, 0.125f);

    // ---- softmax + batch-sum -> bf16 hi/lo att ----
    softmax_sum_kernel<<<NHEAD * SEQ, 256>>>(sc, mask, atth, attl);

    // ---- AV: av[b,:,h*64+d] = att_h @ vt_bh^T  (N=64, K=1024) ----
    mm3_kernel<64><<<dim3(1, SEQ / 128, NB * NHEAD), 256, SMEM64>>>(
        atth, attl, 0, SS, SEQ,
        vth, vtl, (size_t)NHEAD * HDIM * SEQ, (size_t)HDIM * SEQ, SEQ,
        nullptr, av, SDM, (size_t)HDIM, DM, SEQ, 1.f);

    // ---- output projection ----
    split_bf16_kernel<<<n4_act / 256, 256>>>(av, avh, avl, n4_act);
    mm3_kernel<128><<<pgrid, 256, SMEM128>>>(avh, avl, 0, 0, DM, woh, wol, 0, 0, DM,
                                             bo, out, 0, 0, DM, DM, 1.f);
}